// round 8
// baseline (speedup 1.0000x reference)
#include <cuda_runtime.h>
#include <cstdint>
#include <cstddef>

#define B_ 8
#define S_ 2048
#define D_ 1024
#define MTOK (B_ * S_)
#define NELEM ((size_t)MTOK * D_)
#define SB_ ((long long)S_ * D_)
#define SL_ ((long long)S_ * S_)

// ---- static device scratch (allocation-free rule) ----
__device__ __align__(16) float g_X[3 * NELEM];             // tf32-rounded inputs
__device__ __align__(16) float g_P[3 * NELEM];             // projected Q,K,V
__device__ __align__(16) float g_L[(size_t)B_ * S_ * S_];  // logits / weights
__device__ __align__(16) float g_VT[(size_t)B_ * D_ * S_]; // V^T per batch
__device__ __align__(16) float g_WT[(size_t)D_ * D_];      // W^T

// ---- helpers ----
__device__ __forceinline__ float tf32r(float x) {
    uint32_t u;
    asm("cvt.rna.tf32.f32 %0, %1;" : "=r"(u) : "f"(x));
    return __uint_as_float(u);
}
__device__ __forceinline__ uint32_t smem_u32(const void* p) {
    uint32_t a;
    asm("{ .reg .u64 t; cvta.to.shared.u64 t, %1; cvt.u32.u64 %0, t; }" : "=r"(a) : "l"(p));
    return a;
}
__device__ __forceinline__ void cp16(uint32_t s, const void* g) {
    asm volatile("cp.async.cg.shared.global [%0], [%1], 16;" :: "r"(s), "l"(g) : "memory");
}
__device__ __forceinline__ void mma_tf32(float* c, const uint32_t* a, const uint32_t* b) {
    asm volatile(
        "mma.sync.aligned.m16n8k8.row.col.f32.tf32.tf32.f32 "
        "{%0,%1,%2,%3}, {%4,%5,%6,%7}, {%8,%9}, {%0,%1,%2,%3};"
        : "+f"(c[0]), "+f"(c[1]), "+f"(c[2]), "+f"(c[3])
        : "r"(a[0]), "r"(a[1]), "r"(a[2]), "r"(a[3]), "r"(b[0]), "r"(b[1]));
}

// ---- tf32 GEMM: C[M,N] = scale*(A[M,K] @ B[N,K]^T) (+bias), 128x128x32 tiles ----
#define BKF 32
#define LDA 36                      // 32 + 4 pad floats (keeps 16B alignment)
#define ASTG (128 * LDA)            // 4608 floats per operand stage
#define STGF (2 * ASTG)             // floats per stage (A + B)
#define GSMEM_FLOATS (128 + 3 * STGF)
#define GSMEM_BYTES (GSMEM_FLOATS * 4)

__device__ __forceinline__ void load_tile(const float* __restrict__ src, int ld,
                                          int row0, int k0, float* st, int tid) {
#pragma unroll
    for (int i = 0; i < 4; i++) {
        int idx = i * 256 + tid;         // 1024 chunks of 16B
        int r = idx >> 3, c = idx & 7;
        cp16(smem_u32(st + r * LDA + c * 4),
             src + (size_t)(row0 + r) * ld + (k0 + c * 4));
    }
}

__global__ void __launch_bounds__(256) gemm_tf32(
    const float* __restrict__ A, const float* __restrict__ Bm,
    float* __restrict__ C, const float* __restrict__ bias,
    float scale, int round_out, int K, int N,
    long long sA, long long sB, long long sC)
{
    extern __shared__ float sm[];
    float* bias_s = sm;
    float* tiles  = sm + 128;

    const int tid = threadIdx.x, wid = tid >> 5, lane = tid & 31;
    const int g = lane >> 2, t = lane & 3;
    const int wm = (wid & 3) * 32;       // warp M offset in tile
    const int wn = (wid >> 2) * 64;      // warp N offset in tile
    const int m0 = blockIdx.x * 128, n0 = blockIdx.y * 128;

    A  += (long long)blockIdx.z * sA;
    Bm += (long long)blockIdx.z * sB;
    C  += (long long)blockIdx.z * sC;

    if (bias && tid < 128) bias_s[tid] = bias[n0 + tid];

    const int nK = K >> 5;

    // prologue: stages 0,1
#pragma unroll
    for (int p = 0; p < 2; p++) {
        load_tile(A,  K, m0, p * BKF, tiles + p * STGF, tid);
        load_tile(Bm, K, n0, p * BKF, tiles + p * STGF + ASTG, tid);
        asm volatile("cp.async.commit_group;" ::: "memory");
    }

    float acc[2][8][4];
#pragma unroll
    for (int mi = 0; mi < 2; mi++)
#pragma unroll
        for (int nj = 0; nj < 8; nj++)
#pragma unroll
            for (int q = 0; q < 4; q++) acc[mi][nj][q] = 0.0f;

    for (int s = 0; s < nK; s++) {
        __syncthreads();                       // compute(s-1) done before overwrite
        if (s + 2 < nK) {
            float* st = tiles + ((s + 2) % 3) * STGF;
            load_tile(A,  K, m0, (s + 2) * BKF, st, tid);
            load_tile(Bm, K, n0, (s + 2) * BKF, st + ASTG, tid);
        }
        asm volatile("cp.async.commit_group;" ::: "memory");
        asm volatile("cp.async.wait_group 2;" ::: "memory");   // stage s resident
        __syncthreads();

        const float* As = tiles + (s % 3) * STGF;
        const float* Bs = As + ASTG;

#pragma unroll
        for (int ks = 0; ks < 4; ks++) {
            const int kb = ks * 8;
            uint32_t a[2][4], b[8][2];
#pragma unroll
            for (int mi = 0; mi < 2; mi++) {
                const float* ap = As + (wm + mi * 16 + g) * LDA + kb + t;
                a[mi][0] = __float_as_uint(ap[0]);
                a[mi][1] = __float_as_uint(ap[8 * LDA]);
                a[mi][2] = __float_as_uint(ap[4]);
                a[mi][3] = __float_as_uint(ap[8 * LDA + 4]);
            }
#pragma unroll
            for (int nj = 0; nj < 8; nj++) {
                const float* bp = Bs + (wn + nj * 8 + g) * LDA + kb + t;
                b[nj][0] = __float_as_uint(bp[0]);
                b[nj][1] = __float_as_uint(bp[4]);
            }
#pragma unroll
            for (int mi = 0; mi < 2; mi++)
#pragma unroll
                for (int nj = 0; nj < 8; nj++)
                    mma_tf32(acc[mi][nj], a[mi], b[nj]);
        }
    }

    __syncthreads();
    const bool hb = (bias != nullptr);
#pragma unroll
    for (int mi = 0; mi < 2; mi++) {
#pragma unroll
        for (int nj = 0; nj < 8; nj++) {
            int row = m0 + wm + mi * 16 + g;
            int col = n0 + wn + nj * 8 + 2 * t;
            float b0 = hb ? bias_s[wn + nj * 8 + 2 * t]     : 0.0f;
            float b1 = hb ? bias_s[wn + nj * 8 + 2 * t + 1] : 0.0f;
            float2 v0, v1;
            v0.x = acc[mi][nj][0] * scale + b0;
            v0.y = acc[mi][nj][1] * scale + b1;
            v1.x = acc[mi][nj][2] * scale + b0;
            v1.y = acc[mi][nj][3] * scale + b1;
            if (round_out) {
                v0.x = tf32r(v0.x); v0.y = tf32r(v0.y);
                v1.x = tf32r(v1.x); v1.y = tf32r(v1.y);
            }
            *(float2*)(C + (size_t)row * N + col)       = v0;
            *(float2*)(C + (size_t)(row + 8) * N + col) = v1;
        }
    }
}

// ---- tf32-round copy ----
__global__ void __launch_bounds__(256) round_copy(const float* __restrict__ in,
                                                  float* __restrict__ out) {
    size_t i = (size_t)blockIdx.x * blockDim.x + threadIdx.x;
    float4 v = ((const float4*)in)[i];
    v.x = tf32r(v.x); v.y = tf32r(v.y); v.z = tf32r(v.z); v.w = tf32r(v.w);
    ((float4*)out)[i] = v;
}

// ---- tiled transpose with tf32 rounding: out[c][r] = rna(in[r][c]) ----
__global__ void __launch_bounds__(256) transpose_round(
    const float* __restrict__ in, float* __restrict__ out,
    int rows, int cols, long long sIn, long long sOut)
{
    __shared__ float tbuf[32][33];
    in  += (long long)blockIdx.z * sIn;
    out += (long long)blockIdx.z * sOut;
    int c0 = blockIdx.x * 32, r0 = blockIdx.y * 32;
    int x = threadIdx.x & 31, y = threadIdx.x >> 5;
#pragma unroll
    for (int i = 0; i < 32; i += 8)
        tbuf[y + i][x] = in[(size_t)(r0 + y + i) * cols + c0 + x];
    __syncthreads();
#pragma unroll
    for (int i = 0; i < 32; i += 8)
        out[(size_t)(c0 + y + i) * rows + r0 + x] = tf32r(tbuf[x][y + i]);
}

// ---- row softmax (2048 cols, 256 threads/row), tf32-rounded store ----
__global__ void __launch_bounds__(256) softmax_rows(float* __restrict__ P) {
    float* r = P + (size_t)blockIdx.x * 2048;
    const int tid = threadIdx.x, lane = tid & 31, wid = tid >> 5;
    __shared__ float red[8];

    float4 a = *(const float4*)(r + tid * 4);
    float4 b = *(const float4*)(r + 1024 + tid * 4);

    float m = fmaxf(fmaxf(fmaxf(a.x, a.y), fmaxf(a.z, a.w)),
                    fmaxf(fmaxf(b.x, b.y), fmaxf(b.z, b.w)));
#pragma unroll
    for (int o = 16; o; o >>= 1) m = fmaxf(m, __shfl_xor_sync(~0u, m, o));
    if (lane == 0) red[wid] = m;
    __syncthreads();
    m = red[0];
#pragma unroll
    for (int i = 1; i < 8; i++) m = fmaxf(m, red[i]);
    __syncthreads();

    a.x = expf(a.x - m); a.y = expf(a.y - m); a.z = expf(a.z - m); a.w = expf(a.w - m);
    b.x = expf(b.x - m); b.y = expf(b.y - m); b.z = expf(b.z - m); b.w = expf(b.w - m);
    float s = a.x + a.y + a.z + a.w + b.x + b.y + b.z + b.w;
#pragma unroll
    for (int o = 16; o; o >>= 1) s += __shfl_xor_sync(~0u, s, o);
    if (lane == 0) red[wid] = s;
    __syncthreads();
    s = red[0];
#pragma unroll
    for (int i = 1; i < 8; i++) s += red[i];
    float inv = 1.0f / s;

    a.x = tf32r(a.x * inv); a.y = tf32r(a.y * inv); a.z = tf32r(a.z * inv); a.w = tf32r(a.w * inv);
    b.x = tf32r(b.x * inv); b.y = tf32r(b.y * inv); b.z = tf32r(b.z * inv); b.w = tf32r(b.w * inv);
    *(float4*)(r + tid * 4) = a;
    *(float4*)(r + 1024 + tid * 4) = b;
}

// ---- host launcher ----
extern "C" void kernel_launch(void* const* d_in, const int* in_sizes, int n_in,
                              void* d_out, int out_size) {
    const float* q  = (const float*)d_in[0];
    const float* k  = (const float*)d_in[1];
    const float* v  = (const float*)d_in[2];
    const float* Wq = (const float*)d_in[3];
    const float* bq = (const float*)d_in[4];
    float* out = (float*)d_out;

    float *pX, *pP, *pL, *pVT, *pWT;
    cudaGetSymbolAddress((void**)&pX,  g_X);
    cudaGetSymbolAddress((void**)&pP,  g_P);
    cudaGetSymbolAddress((void**)&pL,  g_L);
    cudaGetSymbolAddress((void**)&pVT, g_VT);
    cudaGetSymbolAddress((void**)&pWT, g_WT);

    cudaFuncSetAttribute(gemm_tf32, cudaFuncAttributeMaxDynamicSharedMemorySize, GSMEM_BYTES);

    // 1) round inputs to tf32-exact fp32
    round_copy<<<16384, 256>>>(q, pX);
    round_copy<<<16384, 256>>>(k, pX + NELEM);
    round_copy<<<16384, 256>>>(v, pX + 2 * NELEM);
    // 2) W^T (K-major B operand), rounded
    transpose_round<<<dim3(32, 32, 1), 256>>>(Wq, pWT, D_, D_, 0, 0);
    // 3) fused projections: [3*16384,1024] = X @ W + b, tf32-rounded outputs
    gemm_tf32<<<dim3(384, 8, 1), 256, GSMEM_BYTES>>>(
        pX, pWT, pP, bq, 1.0f, 1, D_, D_, 0, 0, 0);
    // 4) logits = Q @ K^T / 32
    gemm_tf32<<<dim3(16, 16, 8), 256, GSMEM_BYTES>>>(
        pP, pP + NELEM, pL, nullptr, 0.03125f, 0, D_, S_, SB_, SB_, SL_);
    // 5) softmax rows (tf32-rounded weights)
    softmax_rows<<<B_ * S_, 256>>>(pL);
    // 6) V^T per batch (rounded)
    transpose_round<<<dim3(32, 64, 8), 256>>>(pP + 2 * NELEM, pVT, S_, D_, SB_, SB_);
    // 7) out = weights @ V
    gemm_tf32<<<dim3(16, 8, 8), 256, GSMEM_BYTES>>>(
        pL, pVT, out, nullptr, 1.0f, 0, S_, D_, SL_, SB_, SB_);
}